// round 12
// baseline (speedup 1.0000x reference)
#include <cuda_runtime.h>

#define NN   100000
#define FIN  128
#define H    24
#define C    16
#define EMAX 3200000

// Scratch (device globals — no allocation allowed), 16B-aligned for float4 ops
__device__ __align__(16) int   g_deg[NN];
__device__ __align__(16) int   g_rs[NN + 1];     // CSR row starts (by dst)
__device__ __align__(16) int   g_cur[NN];        // fill cursors
__device__ __align__(16) int   g_srcs[EMAX];     // src node per CSR slot
__device__ __align__(16) float g_dinv[NN];
__device__ __align__(16) float g_hs1[NN * H];    // dinv[i] * (x[i] @ W1)
__device__ __align__(16) float g_acc1[NN * H];   // sum of incoming hs1
__device__ __align__(16) float g_hs2[NN * C];    // dinv[i] * (relu(layer1) @ W2)
__device__ __align__(16) float g_acc2[NN * C];

// ---------------------------------------------------------------- zero degrees
__global__ void k_zero() {
    int i = blockIdx.x * blockDim.x + threadIdx.x;
    if (i < NN) g_deg[i] = 0;
}

// ---------------------------------------------------------------- degree
__global__ void k_deg(const int* __restrict__ dst, int E) {
    int i = blockIdx.x * blockDim.x + threadIdx.x;
    if (i < E) atomicAdd(&g_deg[dst[i]], 1);
}

__global__ void k_dinv() {
    int i = blockIdx.x * blockDim.x + threadIdx.x;
    if (i < NN) g_dinv[i] = rsqrtf((float)g_deg[i] + 1.0f);  // +1 = self loop
}

// ---------------------------------------------------------------- prefix scan (1 block, 1024 thr)
__global__ void __launch_bounds__(1024) k_scan() {
    __shared__ int buf[2][1024];
    int t = threadIdx.x;
    const int per = (NN + 1023) / 1024;      // 98
    int lo = t * per;
    int hi = lo + per; if (hi > NN) hi = NN;
    int s = 0;
    for (int i = lo; i < hi; i++) s += g_deg[i];
    buf[0][t] = s;
    __syncthreads();
    int cur = 0;
    for (int o = 1; o < 1024; o <<= 1) {     // double-buffered inclusive scan
        int nxt = cur ^ 1;
        int v = buf[cur][t];
        if (t >= o) v += buf[cur][t - o];
        buf[nxt][t] = v;
        __syncthreads();
        cur = nxt;
    }
    int run = (t > 0) ? buf[cur][t - 1] : 0;
    for (int i = lo; i < hi; i++) {
        g_rs[i] = run; g_cur[i] = run;
        run += g_deg[i];
    }
    if (t == 1023) g_rs[NN] = run;
}

// ---------------------------------------------------------------- CSR fill (counting sort)
__global__ void k_fill(const int* __restrict__ dst, const int* __restrict__ src, int E) {
    int i = blockIdx.x * blockDim.x + threadIdx.x;
    if (i < E) {
        int d = dst[i];
        int p = atomicAdd(&g_cur[d], 1);
        g_srcs[p] = src[i];
    }
}

// ---------------------------------------------------------------- GEMM1: hs1 = dinv * (x @ W1)
// 160 nodes/block, 160 threads: tile = 2 nodes x 12 outputs per thread.
// K split into 4 chunks of 32 (Xs 160x33 padded, conflict-free).
__global__ void __launch_bounds__(160) k_gemm1(const float* __restrict__ x,
                                               const float* __restrict__ W1) {
    __shared__ float Ws[FIN * H];        // [k][24], 12 KB
    __shared__ float Xs[160 * 33];       // 160 rows x 32 (+1 pad), ~21 KB
    int tid = threadIdx.x;
    int base = blockIdx.x * 160;         // 100000 = 625 * 160

    for (int i = tid; i < FIN * H; i += 160) Ws[i] = W1[i];

    int p  = tid >> 1;                   // node pair 0..79
    int og = tid & 1;                    // output half: 12 floats
    int n0 = 2 * p, n1 = 2 * p + 1;

    float a0[12], a1[12];
#pragma unroll
    for (int f = 0; f < 12; f++) { a0[f] = 0.f; a1[f] = 0.f; }

    const float4* x4 = (const float4*)x;
    for (int c = 0; c < 4; c++) {
        __syncthreads();
        // stage chunk: 160 rows x 8 float4
        for (int i = tid; i < 160 * 8; i += 160) {
            int row = i >> 3, k4 = i & 7;
            float4 v = x4[(long long)(base + row) * 32 + c * 8 + k4];
            float* dp = &Xs[row * 33 + k4 * 4];
            dp[0] = v.x; dp[1] = v.y; dp[2] = v.z; dp[3] = v.w;
        }
        __syncthreads();
#pragma unroll 8
        for (int k = 0; k < 32; k++) {
            float x0 = Xs[n0 * 33 + k];
            float x1 = Xs[n1 * 33 + k];
            const float* w = &Ws[(c * 32 + k) * H + og * 12];
#pragma unroll
            for (int f = 0; f < 12; f++) {
                float wf = w[f];
                a0[f] += x0 * wf;
                a1[f] += x1 * wf;
            }
        }
    }
    int node0 = base + n0, node1 = base + n1;
    float d0 = g_dinv[node0], d1 = g_dinv[node1];
#pragma unroll
    for (int f = 0; f < 12; f++) {
        g_hs1[node0 * H + og * 12 + f] = a0[f] * d0;
        g_hs1[node1 * H + og * 12 + f] = a1[f] * d1;
    }
}

// ---------------------------------------------------------------- gather layer 1 (CSR, no atomics)
// 6 threads per dst row; each owns one float4 column, one final store.
__global__ void __launch_bounds__(192) k_scat1() {
    int t = blockIdx.x * 192 + threadIdx.x;
    int g = t / 6;
    if (g >= NN) return;
    int j = t - g * 6;
    int beg = g_rs[g], end = g_rs[g + 1];
    const float4* h4 = (const float4*)g_hs1;
    float4 acc = make_float4(0.f, 0.f, 0.f, 0.f);
    int e = beg;
    for (; e + 1 < end; e += 2) {
        int s0 = g_srcs[e], s1 = g_srcs[e + 1];
        float4 v0 = h4[s0 * 6 + j];
        float4 v1 = h4[s1 * 6 + j];
        acc.x += v0.x + v1.x; acc.y += v0.y + v1.y;
        acc.z += v0.z + v1.z; acc.w += v0.w + v1.w;
    }
    if (e < end) {
        int s = g_srcs[e];
        float4 v = h4[s * 6 + j];
        acc.x += v.x; acc.y += v.y; acc.z += v.z; acc.w += v.w;
    }
    ((float4*)g_acc1)[g * 6 + j] = acc;
}

// ---------------------------------------------------------------- fused: relu + GEMM2
__global__ void __launch_bounds__(384) k_gemm2(const float* __restrict__ b1,
                                               const float* __restrict__ W2) {
    __shared__ float W2s[H * C];
    __shared__ float b1s[H];
    __shared__ float rs[16 * H];
    int tid = threadIdx.x;
    if (tid < H * C) W2s[tid] = W2[tid];
    if (tid < H)     b1s[tid] = b1[tid];
    __syncthreads();

    int base = blockIdx.x * 16;      // NN % 16 == 0
    int nl = tid / H, k = tid % H;
    int node = base + nl;
    float a = g_acc1[node * H + k] + g_hs1[node * H + k];   // + self loop
    rs[nl * H + k] = fmaxf(g_dinv[node] * a + b1s[k], 0.f);
    __syncthreads();

    if (tid < 256) {
        int nl2 = tid / C, c = tid % C;
        int node2 = base + nl2;
        float s = 0.f;
#pragma unroll
        for (int kk = 0; kk < H; kk++) s += rs[nl2 * H + kk] * W2s[kk * C + c];
        g_hs2[node2 * C + c] = s * g_dinv[node2];
    }
}

// ---------------------------------------------------------------- gather layer 2 (CSR, no atomics)
// 4 threads per dst row.
__global__ void __launch_bounds__(256) k_scat2() {
    int t = blockIdx.x * 256 + threadIdx.x;
    int g = t >> 2;
    if (g >= NN) return;
    int j = t & 3;
    int beg = g_rs[g], end = g_rs[g + 1];
    const float4* h4 = (const float4*)g_hs2;
    float4 acc = make_float4(0.f, 0.f, 0.f, 0.f);
    int e = beg;
    for (; e + 1 < end; e += 2) {
        int s0 = g_srcs[e], s1 = g_srcs[e + 1];
        float4 v0 = h4[s0 * 4 + j];
        float4 v1 = h4[s1 * 4 + j];
        acc.x += v0.x + v1.x; acc.y += v0.y + v1.y;
        acc.z += v0.z + v1.z; acc.w += v0.w + v1.w;
    }
    if (e < end) {
        int s = g_srcs[e];
        float4 v = h4[s * 4 + j];
        acc.x += v.x; acc.y += v.y; acc.z += v.z; acc.w += v.w;
    }
    ((float4*)g_acc2)[g * 4 + j] = acc;
}

// ---------------------------------------------------------------- epilogue: log_softmax
__global__ void k_out(const float* __restrict__ b2, float* __restrict__ out) {
    int g = blockIdx.x * blockDim.x + threadIdx.x;
    int node = g >> 4, c = g & 15;
    if (node >= NN) return;
    float v = g_dinv[node] * (g_acc2[node * C + c] + g_hs2[node * C + c]) + b2[c];
    float m = v;
#pragma unroll
    for (int o = 8; o; o >>= 1) m = fmaxf(m, __shfl_xor_sync(0xffffffffu, m, o, 16));
    float s = expf(v - m);
#pragma unroll
    for (int o = 8; o; o >>= 1) s += __shfl_xor_sync(0xffffffffu, s, o, 16);
    out[node * C + c] = (v - m) - logf(s);
}

// ---------------------------------------------------------------- launch
extern "C" void kernel_launch(void* const* d_in, const int* in_sizes, int n_in,
                              void* d_out, int out_size) {
    const float* x   = (const float*)d_in[0];
    const int*   ei  = (const int*)d_in[1];    // [2, E] — int32 (JAX x64 disabled)
    const float* W1  = (const float*)d_in[2];
    const float* b1  = (const float*)d_in[3];
    const float* W2  = (const float*)d_in[4];
    const float* b2  = (const float*)d_in[5];
    float*       out = (float*)d_out;

    int E = in_sizes[1] / 2;
    const int* dst = ei;        // edge_index[0] = row = target
    const int* src = ei + E;    // edge_index[1] = col = source

    k_zero<<<(NN + 255) / 256, 256>>>();
    k_deg<<<(E + 255) / 256, 256>>>(dst, E);
    k_dinv<<<(NN + 255) / 256, 256>>>();
    k_scan<<<1, 1024>>>();
    k_fill<<<(E + 255) / 256, 256>>>(dst, src, E);

    k_gemm1<<<NN / 160, 160>>>(x, W1);

    {
        long long tot = (long long)NN * 6;
        k_scat1<<<(int)((tot + 191) / 192), 192>>>();
    }

    k_gemm2<<<NN / 16, 384>>>(b1, W2);

    {
        long long tot = (long long)NN * 4;
        k_scat2<<<(int)((tot + 255) / 256), 256>>>();
    }

    {
        long long tot = (long long)NN * 16;
        k_out<<<(int)((tot + 255) / 256), 256>>>(b2, out);
    }
}

// round 16
// speedup vs baseline: 1.9422x; 1.9422x over previous
#include <cuda_runtime.h>

#define NN   100000
#define FIN  128
#define H    24
#define C    16
#define EMAX 3200000
#define SCAN_BS   512
#define SCAN_GRID ((NN + SCAN_BS - 1) / SCAN_BS)   // 196

// Scratch (device globals — no allocation allowed), 16B-aligned for float4 ops
__device__ __align__(16) int   g_deg[NN];
__device__ __align__(16) int   g_bsum[SCAN_GRID];
__device__ __align__(16) int   g_boff[SCAN_GRID];
__device__ __align__(16) int   g_rs[NN + 1];     // CSR row starts (by dst)
__device__ __align__(16) int   g_cur[NN];        // fill cursors
__device__ __align__(16) int   g_srcs[EMAX];     // src node per CSR slot
__device__ __align__(16) float g_dinv[NN];
__device__ __align__(16) float g_hs1[NN * H];    // dinv[i] * (x[i] @ W1)
__device__ __align__(16) float g_acc1[NN * H];   // sum of incoming hs1
__device__ __align__(16) float g_hs2[NN * C];    // dinv[i] * (relu(layer1) @ W2)
__device__ __align__(16) float g_acc2[NN * C];

// ---------------------------------------------------------------- zero degrees
__global__ void k_zero() {
    int i = blockIdx.x * blockDim.x + threadIdx.x;
    if (i < NN) g_deg[i] = 0;
}

// ---------------------------------------------------------------- degree
__global__ void k_deg(const int* __restrict__ dst, int E) {
    int i = blockIdx.x * blockDim.x + threadIdx.x;
    if (i < E) atomicAdd(&g_deg[dst[i]], 1);
}

// ---------------------------------------------------------------- scan phase A: block sums
__global__ void __launch_bounds__(SCAN_BS) k_scan_a() {
    __shared__ int ws[SCAN_BS / 32];
    int i = blockIdx.x * SCAN_BS + threadIdx.x;
    int v = (i < NN) ? g_deg[i] : 0;
    int s = v;
#pragma unroll
    for (int o = 16; o; o >>= 1) s += __shfl_down_sync(0xffffffffu, s, o);
    int wid = threadIdx.x >> 5, lane = threadIdx.x & 31;
    if (lane == 0) ws[wid] = s;
    __syncthreads();
    if (threadIdx.x == 0) {
        int t = 0;
#pragma unroll
        for (int w = 0; w < SCAN_BS / 32; w++) t += ws[w];
        g_bsum[blockIdx.x] = t;
    }
}

// ---------------------------------------------------------------- scan phase B: scan block sums (1 block)
__global__ void __launch_bounds__(256) k_scan_b() {
    __shared__ int buf[2][256];
    int t = threadIdx.x;
    int v = (t < SCAN_GRID) ? g_bsum[t] : 0;
    buf[0][t] = v;
    __syncthreads();
    int cur = 0;
    for (int o = 1; o < 256; o <<= 1) {
        int nxt = cur ^ 1;
        int s = buf[cur][t];
        if (t >= o) s += buf[cur][t - o];
        buf[nxt][t] = s;
        __syncthreads();
        cur = nxt;
    }
    if (t < SCAN_GRID) g_boff[t] = buf[cur][t] - v;   // exclusive
    if (t == 255) g_rs[NN] = buf[cur][SCAN_GRID - 1];
}

// ---------------------------------------------------------------- scan phase C: in-block scan + offset (+ dinv fused)
__global__ void __launch_bounds__(SCAN_BS) k_scan_c() {
    __shared__ int ws[SCAN_BS / 32];
    int i = blockIdx.x * SCAN_BS + threadIdx.x;
    int v = (i < NN) ? g_deg[i] : 0;
    int lane = threadIdx.x & 31, wid = threadIdx.x >> 5;
    int incl = v;
#pragma unroll
    for (int o = 1; o < 32; o <<= 1) {
        int u = __shfl_up_sync(0xffffffffu, incl, o);
        if (lane >= o) incl += u;
    }
    if (lane == 31) ws[wid] = incl;
    __syncthreads();
    if (wid == 0) {
        int wv = (lane < SCAN_BS / 32) ? ws[lane] : 0;
#pragma unroll
        for (int o = 1; o < SCAN_BS / 32; o <<= 1) {
            int u = __shfl_up_sync(0xffffffffu, wv, o);
            if (lane >= o) wv += u;
        }
        if (lane < SCAN_BS / 32) ws[lane] = wv;
    }
    __syncthreads();
    int ex = incl - v + (wid ? ws[wid - 1] : 0) + g_boff[blockIdx.x];
    if (i < NN) {
        g_rs[i] = ex; g_cur[i] = ex;
        g_dinv[i] = rsqrtf((float)v + 1.0f);   // +1 = self loop
    }
}

// ---------------------------------------------------------------- CSR fill (counting sort)
__global__ void k_fill(const int* __restrict__ dst, const int* __restrict__ src, int E) {
    int i = blockIdx.x * blockDim.x + threadIdx.x;
    if (i < E) {
        int d = dst[i];
        int p = atomicAdd(&g_cur[d], 1);
        g_srcs[p] = src[i];
    }
}

// ---------------------------------------------------------------- GEMM1: hs1 = dinv * (x @ W1)
// 160 nodes/block, 160 threads: tile = 2 nodes x 12 outputs per thread.
__global__ void __launch_bounds__(160) k_gemm1(const float* __restrict__ x,
                                               const float* __restrict__ W1) {
    __shared__ float Ws[FIN * H];        // 12 KB
    __shared__ float Xs[160 * 33];       // ~21 KB
    int tid = threadIdx.x;
    int base = blockIdx.x * 160;         // 100000 = 625 * 160

    for (int i = tid; i < FIN * H; i += 160) Ws[i] = W1[i];

    int p  = tid >> 1;
    int og = tid & 1;
    int n0 = 2 * p, n1 = 2 * p + 1;

    float a0[12], a1[12];
#pragma unroll
    for (int f = 0; f < 12; f++) { a0[f] = 0.f; a1[f] = 0.f; }

    const float4* x4 = (const float4*)x;
    for (int c = 0; c < 4; c++) {
        __syncthreads();
        for (int i = tid; i < 160 * 8; i += 160) {
            int row = i >> 3, k4 = i & 7;
            float4 v = x4[(long long)(base + row) * 32 + c * 8 + k4];
            float* dp = &Xs[row * 33 + k4 * 4];
            dp[0] = v.x; dp[1] = v.y; dp[2] = v.z; dp[3] = v.w;
        }
        __syncthreads();
#pragma unroll 8
        for (int k = 0; k < 32; k++) {
            float x0 = Xs[n0 * 33 + k];
            float x1 = Xs[n1 * 33 + k];
            const float* w = &Ws[(c * 32 + k) * H + og * 12];
#pragma unroll
            for (int f = 0; f < 12; f++) {
                float wf = w[f];
                a0[f] += x0 * wf;
                a1[f] += x1 * wf;
            }
        }
    }
    int node0 = base + n0, node1 = base + n1;
    float d0 = g_dinv[node0], d1 = g_dinv[node1];
#pragma unroll
    for (int f = 0; f < 12; f++) {
        g_hs1[node0 * H + og * 12 + f] = a0[f] * d0;
        g_hs1[node1 * H + og * 12 + f] = a1[f] * d1;
    }
}

// ---------------------------------------------------------------- gather layer 1 (CSR, no atomics)
__global__ void __launch_bounds__(192) k_scat1() {
    int t = blockIdx.x * 192 + threadIdx.x;
    int g = t / 6;
    if (g >= NN) return;
    int j = t - g * 6;
    int beg = g_rs[g], end = g_rs[g + 1];
    const float4* h4 = (const float4*)g_hs1;
    float4 acc = make_float4(0.f, 0.f, 0.f, 0.f);
    int e = beg;
    for (; e + 1 < end; e += 2) {
        int s0 = g_srcs[e], s1 = g_srcs[e + 1];
        float4 v0 = h4[s0 * 6 + j];
        float4 v1 = h4[s1 * 6 + j];
        acc.x += v0.x + v1.x; acc.y += v0.y + v1.y;
        acc.z += v0.z + v1.z; acc.w += v0.w + v1.w;
    }
    if (e < end) {
        int s = g_srcs[e];
        float4 v = h4[s * 6 + j];
        acc.x += v.x; acc.y += v.y; acc.z += v.z; acc.w += v.w;
    }
    ((float4*)g_acc1)[g * 6 + j] = acc;
}

// ---------------------------------------------------------------- fused: relu + GEMM2
__global__ void __launch_bounds__(384) k_gemm2(const float* __restrict__ b1,
                                               const float* __restrict__ W2) {
    __shared__ float W2s[H * C];
    __shared__ float b1s[H];
    __shared__ float rs[16 * H];
    int tid = threadIdx.x;
    if (tid < H * C) W2s[tid] = W2[tid];
    if (tid < H)     b1s[tid] = b1[tid];
    __syncthreads();

    int base = blockIdx.x * 16;
    int nl = tid / H, k = tid % H;
    int node = base + nl;
    float a = g_acc1[node * H + k] + g_hs1[node * H + k];   // + self loop
    rs[nl * H + k] = fmaxf(g_dinv[node] * a + b1s[k], 0.f);
    __syncthreads();

    if (tid < 256) {
        int nl2 = tid / C, c = tid % C;
        int node2 = base + nl2;
        float s = 0.f;
#pragma unroll
        for (int kk = 0; kk < H; kk++) s += rs[nl2 * H + kk] * W2s[kk * C + c];
        g_hs2[node2 * C + c] = s * g_dinv[node2];
    }
}

// ---------------------------------------------------------------- gather layer 2 (CSR, no atomics)
__global__ void __launch_bounds__(256) k_scat2() {
    int t = blockIdx.x * 256 + threadIdx.x;
    int g = t >> 2;
    if (g >= NN) return;
    int j = t & 3;
    int beg = g_rs[g], end = g_rs[g + 1];
    const float4* h4 = (const float4*)g_hs2;
    float4 acc = make_float4(0.f, 0.f, 0.f, 0.f);
    int e = beg;
    for (; e + 1 < end; e += 2) {
        int s0 = g_srcs[e], s1 = g_srcs[e + 1];
        float4 v0 = h4[s0 * 4 + j];
        float4 v1 = h4[s1 * 4 + j];
        acc.x += v0.x + v1.x; acc.y += v0.y + v1.y;
        acc.z += v0.z + v1.z; acc.w += v0.w + v1.w;
    }
    if (e < end) {
        int s = g_srcs[e];
        float4 v = h4[s * 4 + j];
        acc.x += v.x; acc.y += v.y; acc.z += v.z; acc.w += v.w;
    }
    ((float4*)g_acc2)[g * 4 + j] = acc;
}

// ---------------------------------------------------------------- epilogue: log_softmax
__global__ void k_out(const float* __restrict__ b2, float* __restrict__ out) {
    int g = blockIdx.x * blockDim.x + threadIdx.x;
    int node = g >> 4, c = g & 15;
    if (node >= NN) return;
    float v = g_dinv[node] * (g_acc2[node * C + c] + g_hs2[node * C + c]) + b2[c];
    float m = v;
#pragma unroll
    for (int o = 8; o; o >>= 1) m = fmaxf(m, __shfl_xor_sync(0xffffffffu, m, o, 16));
    float s = expf(v - m);
#pragma unroll
    for (int o = 8; o; o >>= 1) s += __shfl_xor_sync(0xffffffffu, s, o, 16);
    out[node * C + c] = (v - m) - logf(s);
}

// ---------------------------------------------------------------- launch
extern "C" void kernel_launch(void* const* d_in, const int* in_sizes, int n_in,
                              void* d_out, int out_size) {
    const float* x   = (const float*)d_in[0];
    const int*   ei  = (const int*)d_in[1];    // [2, E] — int32 (JAX x64 disabled)
    const float* W1  = (const float*)d_in[2];
    const float* b1  = (const float*)d_in[3];
    const float* W2  = (const float*)d_in[4];
    const float* b2  = (const float*)d_in[5];
    float*       out = (float*)d_out;

    int E = in_sizes[1] / 2;
    const int* dst = ei;        // edge_index[0] = row = target
    const int* src = ei + E;    // edge_index[1] = col = source

    k_zero<<<(NN + 255) / 256, 256>>>();
    k_deg<<<(E + 255) / 256, 256>>>(dst, E);
    k_scan_a<<<SCAN_GRID, SCAN_BS>>>();
    k_scan_b<<<1, 256>>>();
    k_scan_c<<<SCAN_GRID, SCAN_BS>>>();
    k_fill<<<(E + 255) / 256, 256>>>(dst, src, E);

    k_gemm1<<<NN / 160, 160>>>(x, W1);

    {
        long long tot = (long long)NN * 6;
        k_scat1<<<(int)((tot + 191) / 192), 192>>>();
    }

    k_gemm2<<<NN / 16, 384>>>(b1, W2);

    {
        long long tot = (long long)NN * 4;
        k_scat2<<<(int)((tot + 255) / 256), 256>>>();
    }

    {
        long long tot = (long long)NN * 16;
        k_out<<<(int)((tot + 255) / 256), 256>>>(b2, out);
    }
}